// round 15
// baseline (speedup 1.0000x reference)
#include <cuda_runtime.h>
#include <cstdint>

#define NA    57600     // 64*100*9 anchors
#define NLOC  6400      // 64*100
#define FW    100
#define PRE   6000
#define POST  300
#define NW    94        // ceil(6000/64) u64 words
#define CAP   8192
#define NBIN  65536
#define NCO   1024
#define FULL  0xFFFFFFFFu

typedef unsigned long long u64;

// Base anchors (ratios 0.5,1,2 x scales 8,16,32), numpy banker's rounding baked in.
__constant__ float c_base[36] = {
  -84.f,  -40.f,  99.f,  55.f,
 -176.f,  -88.f, 191.f, 103.f,
 -360.f, -184.f, 375.f, 199.f,
  -56.f,  -56.f,  71.f,  71.f,
 -120.f, -120.f, 135.f, 135.f,
 -248.f, -248.f, 263.f, 263.f,
  -36.f,  -80.f,  51.f,  95.f,
  -80.f, -168.f,  95.f, 183.f,
 -168.f, -344.f, 183.f, 359.f
};

// NOTE: g_hist/g_coarse/g_rank/g_cnt must be ZERO on entry to each run.
// They start zero (static init) and are re-zeroed by k_mask each run.
__device__ float4   g_boxes[NA];
__device__ unsigned g_keys[NA];
__device__ unsigned g_hist[NBIN];
__device__ unsigned g_coarse[NCO];
__device__ int      g_cnt;
__device__ unsigned g_B;
__device__ u64      g_cand[CAP];
__device__ int      g_rank[CAP];
__device__ float4   g_top[PRE];
__device__ u64      g_mask[(size_t)PRE * NW];   // triangular: words < i/64 of row i NOT written

// ---------------------------------------------------------------- decode + fine/coarse histograms
__global__ void k_decode(const float* __restrict__ cls,
                         const float* __restrict__ bbox,
                         const int*   __restrict__ ih,
                         const int*   __restrict__ iw) {
    int t = blockIdx.x * blockDim.x + threadIdx.x;
    if (t >= NA) return;
    int a = t / NLOC, loc = t % NLOC;       // coalesced channel reads
    int y = loc / FW, x = loc % FW;
    int ai = loc * 9 + a;                   // reference anchor index

    float s0 = cls[(2 * a)     * NLOC + loc];
    float s1 = cls[(2 * a + 1) * NLOC + loc];
    float m  = fmaxf(s0, s1);
    float e0 = expf(s0 - m), e1 = expf(s1 - m);
    float score = e1 / (e0 + e1);

    float dx = bbox[(4 * a + 0) * NLOC + loc];
    float dy = bbox[(4 * a + 1) * NLOC + loc];
    float dw = bbox[(4 * a + 2) * NLOC + loc];
    float dh = bbox[(4 * a + 3) * NLOC + loc];

    float sx = (float)(x * 16), sy = (float)(y * 16);
    float ax1 = sx + c_base[a * 4 + 0];
    float ay1 = sy + c_base[a * 4 + 1];
    float ax2 = sx + c_base[a * 4 + 2];
    float ay2 = sy + c_base[a * 4 + 3];

    float w  = ax2 - ax1 + 1.0f;
    float h  = ay2 - ay1 + 1.0f;
    float cx = ax1 + 0.5f * w;
    float cy = ay1 + 0.5f * h;

    float pcx = dx * w + cx;
    float pcy = dy * h + cy;
    float pw  = expf(dw) * w;
    float ph  = expf(dh) * h;

    float W = (float)(iw[0] - 1);
    float H = (float)(ih[0] - 1);
    float x1 = fminf(fmaxf(pcx - 0.5f * pw, 0.f), W);
    float y1 = fminf(fmaxf(pcy - 0.5f * ph, 0.f), H);
    float x2 = fminf(fmaxf(pcx + 0.5f * pw, 0.f), W);
    float y2 = fminf(fmaxf(pcy + 0.5f * ph, 0.f), H);

    bool valid = (x2 - x1 + 1.f >= 16.f) && (y2 - y1 + 1.f >= 16.f);
    float s = valid ? score : -1e30f;

    unsigned u = __float_as_uint(s);
    unsigned key = (u & 0x80000000u) ? ~u : (u | 0x80000000u);

    g_keys[t]   = key;
    g_boxes[ai] = make_float4(x1, y1, x2, y2);
    atomicAdd(&g_hist[key >> 16], 1u);
    atomicAdd(&g_coarse[key >> 22], 1u);
}

// ---------------------------------------------------------------- threshold bin via coarse hist (1 block)
__global__ void k_thresh() {
    __shared__ unsigned warpsum[32];
    __shared__ unsigned warpsuf[32];
    int t = threadIdx.x;            // 1024 threads, one per coarse bucket
    int lane = t & 31, warp = t >> 5;

    unsigned c = g_coarse[t];

    unsigned suf = c;
    #pragma unroll
    for (int off = 1; off < 32; off <<= 1) {
        unsigned v = __shfl_down_sync(FULL, suf, off);
        if (lane + off < 32) suf += v;
    }
    if (lane == 0) warpsum[warp] = suf;
    __syncthreads();
    if (warp == 0) {
        unsigned ws = warpsum[lane];
        unsigned s2 = ws;
        #pragma unroll
        for (int off = 1; off < 32; off <<= 1) {
            unsigned v = __shfl_down_sync(FULL, s2, off);
            if (lane + off < 32) s2 += v;
        }
        warpsuf[lane] = s2 - ws;
    }
    __syncthreads();

    unsigned suffInc = suf + warpsuf[warp];
    unsigned above   = suffInc - c;
    if (above < PRE && suffInc >= PRE) {
        unsigned run = above;
        int base = t * 64;          // coarse bucket t = fine bins [t*64, t*64+64)
        for (int b = 63; b >= 0; b--) {
            run += g_hist[base + b];
            if (run >= PRE) { g_B = (unsigned)(base + b); break; }
        }
    }
}

// ---------------------------------------------------------------- compact candidates (bin >= threshold bin)
__global__ void k_compact() {
    int t = blockIdx.x * blockDim.x + threadIdx.x;
    if (t >= NA) return;
    unsigned key = g_keys[t];
    if ((key >> 16) >= g_B) {
        int p = atomicAdd(&g_cnt, 1);
        if (p < CAP) {
            int a = t / NLOC, loc = t % NLOC;
            unsigned ai = (unsigned)(loc * 9 + a);
            g_cand[p] = ((u64)key << 32) | (~ai);
        }
    }
}

// ---------------------------------------------------------------- 2D-parallel exact rank (partial counts via atomics)
__global__ void k_rank2d() {
    __shared__ u64 tile[256];
    int cnt = g_cnt; if (cnt > CAP) cnt = CAP;
    if (blockIdx.x * 256 >= cnt || blockIdx.y * 256 >= cnt) return;  // uniform early exit
    int j = blockIdx.y * 256 + threadIdx.x;
    tile[threadIdx.x] = (j < cnt) ? g_cand[j] : 0ULL;   // zeros never beat valid keys
    __syncthreads();
    int p = blockIdx.x * 256 + threadIdx.x;
    if (p >= cnt) return;
    u64 v = g_cand[p];
    int r = 0;
    #pragma unroll 8
    for (int q = 0; q < 256; q++) r += (tile[q] > v);
    if (r) atomicAdd(&g_rank[p], r);
}

// ---------------------------------------------------------------- scatter boxes to rank order
__global__ void k_scatter() {
    int cnt = g_cnt; if (cnt > CAP) cnt = CAP;
    int p = blockIdx.x * 256 + threadIdx.x;
    if (p >= cnt) return;
    int r = g_rank[p];
    if (r < PRE) {
        u64 v = g_cand[p];
        unsigned idx = ~(unsigned)v;
        g_top[r] = g_boxes[idx];
    }
}

// ---------------------------------------------------------------- IoU bitmask (upper-triangular) + state re-zero
__global__ void k_mask() {
    __shared__ float4 sb[64];
    int cb = blockIdx.x, rb = blockIdx.y, t = threadIdx.x;

    // housekeeping for the NEXT run: zero hist/coarse/rank/cnt (safe: all
    // consumers of these ran in earlier kernels of THIS run)
    {
        int bid = blockIdx.y * gridDim.x + blockIdx.x;
        int gt  = bid * 64 + t;
        if (gt < NBIN)                       g_hist[gt] = 0u;
        else if (gt < NBIN + NCO)            g_coarse[gt - NBIN] = 0u;
        else if (gt < NBIN + NCO + CAP)      g_rank[gt - NBIN - NCO] = 0;
        else if (gt == NBIN + NCO + CAP)     g_cnt = 0;
    }

    if (cb < rb) return;           // sub-diagonal: never written, never read
    int i = rb * 64 + t;
    int j0 = cb * 64;
    int jg = j0 + t;
    sb[t] = (jg < PRE) ? g_top[jg] : make_float4(0.f, 0.f, 0.f, 0.f);
    __syncthreads();
    if (i >= PRE) return;
    float4 bi = g_top[i];
    float ai = (bi.z - bi.x) * (bi.w - bi.y);
    u64 bits = 0ULL;
    #pragma unroll 4
    for (int b = 0; b < 64; b++) {
        int j = j0 + b;
        float4 bj = sb[b];
        float aj = (bj.z - bj.x) * (bj.w - bj.y);
        float lx = fmaxf(bi.x, bj.x), ly = fmaxf(bi.y, bj.y);
        float rx = fminf(bi.z, bj.z), ry = fminf(bi.w, bj.w);
        float ww = fmaxf(rx - lx, 0.f), hh = fmaxf(ry - ly, 0.f);
        float inter = ww * hh;
        float iou = inter / (ai + aj - inter);
        if (j > i && j < PRE && iou > 0.7f) bits |= 1ULL << b;
    }
    g_mask[(size_t)i * NW + cb] = bits;
}

// ================================================================ word-level NMS, rotating accumulators
// Suppressed candidates cost zero (diag in smem). Kept rows are OR'd into
// 4 ROTATING accumulator sets so their loads stay independent (MLP), not a
// serial RAW chain. rem words are only consumed at their own chunk boundary,
// where the owner lane folds init|acc[0..3] and broadcasts — one exposed
// latency per chunk instead of one per keep.
__global__ __launch_bounds__(128) void k_nms(float* __restrict__ out) {
    extern __shared__ u64 diag[];      // [NW*64] : diag[j] = g_mask[j][j>>6]
    __shared__ int s_keep[POST];
    __shared__ int s_nk;

    int tid  = threadIdx.x;
    int lane = tid & 31;

    // parallel preload of diagonal blocks (4 warps)
    for (int i = tid; i < NW * 64; i += 128) {
        int c = i >> 6;
        diag[i] = (i < PRE) ? g_mask[(size_t)i * NW + c] : 0ULL;
    }
    __syncthreads();

    if (tid < 32) {
        // init words (lane owns: lane, lane+32, lane+64)
        u64 init0 = 0ULL, init1 = 0ULL, init2 = 0ULL;
        if (lane == 29) init2 = (~0ULL) << 48;   // word 93: indices 6000..6015 invalid
        if (lane >= 30) init2 = ~0ULL;           // words 94,95 don't exist

        u64 a0[4] = {0,0,0,0}, a1[4] = {0,0,0,0}, a2[4] = {0,0,0,0};

        int nk = 0;
        for (int c = 0; c < NW && nk < POST; c++) {
            // owner lane folds word c: init | acc[0..3]  (waits only on ~4
            // independent in-flight loads, not a serial chain)
            u64 w;
            if (c < 32)      w = init0 | a0[0] | a0[1] | a0[2] | a0[3];
            else if (c < 64) w = init1 | a1[0] | a1[1] | a1[2] | a1[3];
            else             w = init2 | a2[0] | a2[1] | a2[2] | a2[3];
            u64 freew = ~__shfl_sync(FULL, w, c & 31);

            while (freew) {
                int b = __ffsll((long long)freew) - 1;
                int j = (c << 6) + b;
                if (lane == 0) s_keep[nk] = j;
                nk++;
                if (nk == POST) break;
                freew &= ~(diag[j] | (1ULL << b));   // in-chunk suppression (smem)
                // OR row j into rotating slot (triangular: words < c unwritten)
                const u64* row = g_mask + (size_t)j * NW;
                int slot = nk & 3;
                if (lane >= c)                          a0[slot] |= row[lane];
                if (lane + 32 >= c)                     a1[slot] |= row[lane + 32];
                if (lane + 64 >= c && lane + 64 < NW)   a2[slot] |= row[lane + 64];
            }
        }
        if (lane == 0) s_nk = nk;
    }
    __syncthreads();
    int nk = s_nk;
    for (int k = tid; k < POST; k += 128) if (k >= nk) s_keep[k] = 0;
    __syncthreads();
    for (int k = tid; k < POST; k += 128) {
        float4 b = g_top[s_keep[k]];
        out[k * 5 + 0] = 0.f;
        out[k * 5 + 1] = b.x;
        out[k * 5 + 2] = b.y;
        out[k * 5 + 3] = b.z;
        out[k * 5 + 4] = b.w;
    }
}

// ---------------------------------------------------------------- launch
extern "C" void kernel_launch(void* const* d_in, const int* in_sizes, int n_in,
                              void* d_out, int out_size) {
    const float* cls  = (const float*)d_in[0];
    const float* bbox = (const float*)d_in[1];
    const int*   ih   = (const int*)d_in[2];
    const int*   iw   = (const int*)d_in[3];
    float* out = (float*)d_out;

    static bool attr_set = false;
    if (!attr_set) {
        cudaFuncSetAttribute(k_nms, cudaFuncAttributeMaxDynamicSharedMemorySize,
                             NW * 64 * (int)sizeof(u64) + 4096);
        attr_set = true;
    }

    k_decode <<<(NA + 255) / 256, 256>>>(cls, bbox, ih, iw);
    k_thresh <<<1, 1024>>>();
    k_compact<<<(NA + 255) / 256, 256>>>();
    k_rank2d <<<dim3(CAP / 256, CAP / 256), 256>>>();
    k_scatter<<<CAP / 256, 256>>>();
    k_mask   <<<dim3(NW, NW), 64>>>();
    k_nms    <<<1, 128, NW * 64 * sizeof(u64)>>>(out);
}

// round 16
// speedup vs baseline: 1.6600x; 1.6600x over previous
#include <cuda_runtime.h>
#include <cstdint>

#define NA    57600     // 64*100*9 anchors
#define NLOC  6400      // 64*100
#define FW    100
#define PRE   6000
#define POST  300
#define NW    94        // ceil(6000/64) u64 words
#define CAP   8192
#define NBIN  65536
#define NCO   1024
#define FULL  0xFFFFFFFFu
#define PB    8         // pending-load buffer (unrolled, register-resident)

typedef unsigned long long u64;

// Base anchors (ratios 0.5,1,2 x scales 8,16,32), numpy banker's rounding baked in.
__constant__ float c_base[36] = {
  -84.f,  -40.f,  99.f,  55.f,
 -176.f,  -88.f, 191.f, 103.f,
 -360.f, -184.f, 375.f, 199.f,
  -56.f,  -56.f,  71.f,  71.f,
 -120.f, -120.f, 135.f, 135.f,
 -248.f, -248.f, 263.f, 263.f,
  -36.f,  -80.f,  51.f,  95.f,
  -80.f, -168.f,  95.f, 183.f,
 -168.f, -344.f, 183.f, 359.f
};

// NOTE: g_hist/g_coarse/g_rank/g_cnt must be ZERO on entry to each run.
// They start zero (static init) and are re-zeroed by k_mask each run.
__device__ float4   g_boxes[NA];
__device__ unsigned g_keys[NA];
__device__ unsigned g_hist[NBIN];
__device__ unsigned g_coarse[NCO];
__device__ int      g_cnt;
__device__ unsigned g_B;
__device__ u64      g_cand[CAP];
__device__ int      g_rank[CAP];
__device__ float4   g_top[PRE];
__device__ u64      g_mask[(size_t)PRE * NW];   // triangular: words < i/64 of row i NOT written

// ---------------------------------------------------------------- decode + fine/coarse histograms
__global__ void k_decode(const float* __restrict__ cls,
                         const float* __restrict__ bbox,
                         const int*   __restrict__ ih,
                         const int*   __restrict__ iw) {
    int t = blockIdx.x * blockDim.x + threadIdx.x;
    if (t >= NA) return;
    int a = t / NLOC, loc = t % NLOC;       // coalesced channel reads
    int y = loc / FW, x = loc % FW;
    int ai = loc * 9 + a;                   // reference anchor index

    float s0 = cls[(2 * a)     * NLOC + loc];
    float s1 = cls[(2 * a + 1) * NLOC + loc];
    float m  = fmaxf(s0, s1);
    float e0 = expf(s0 - m), e1 = expf(s1 - m);
    float score = e1 / (e0 + e1);

    float dx = bbox[(4 * a + 0) * NLOC + loc];
    float dy = bbox[(4 * a + 1) * NLOC + loc];
    float dw = bbox[(4 * a + 2) * NLOC + loc];
    float dh = bbox[(4 * a + 3) * NLOC + loc];

    float sx = (float)(x * 16), sy = (float)(y * 16);
    float ax1 = sx + c_base[a * 4 + 0];
    float ay1 = sy + c_base[a * 4 + 1];
    float ax2 = sx + c_base[a * 4 + 2];
    float ay2 = sy + c_base[a * 4 + 3];

    float w  = ax2 - ax1 + 1.0f;
    float h  = ay2 - ay1 + 1.0f;
    float cx = ax1 + 0.5f * w;
    float cy = ay1 + 0.5f * h;

    float pcx = dx * w + cx;
    float pcy = dy * h + cy;
    float pw  = expf(dw) * w;
    float ph  = expf(dh) * h;

    float W = (float)(iw[0] - 1);
    float H = (float)(ih[0] - 1);
    float x1 = fminf(fmaxf(pcx - 0.5f * pw, 0.f), W);
    float y1 = fminf(fmaxf(pcy - 0.5f * ph, 0.f), H);
    float x2 = fminf(fmaxf(pcx + 0.5f * pw, 0.f), W);
    float y2 = fminf(fmaxf(pcy + 0.5f * ph, 0.f), H);

    bool valid = (x2 - x1 + 1.f >= 16.f) && (y2 - y1 + 1.f >= 16.f);
    float s = valid ? score : -1e30f;

    unsigned u = __float_as_uint(s);
    unsigned key = (u & 0x80000000u) ? ~u : (u | 0x80000000u);

    g_keys[t]   = key;
    g_boxes[ai] = make_float4(x1, y1, x2, y2);
    atomicAdd(&g_hist[key >> 16], 1u);
    atomicAdd(&g_coarse[key >> 22], 1u);
}

// ---------------------------------------------------------------- threshold bin via coarse hist (1 block)
__global__ void k_thresh() {
    __shared__ unsigned warpsum[32];
    __shared__ unsigned warpsuf[32];
    int t = threadIdx.x;            // 1024 threads, one per coarse bucket
    int lane = t & 31, warp = t >> 5;

    unsigned c = g_coarse[t];

    unsigned suf = c;
    #pragma unroll
    for (int off = 1; off < 32; off <<= 1) {
        unsigned v = __shfl_down_sync(FULL, suf, off);
        if (lane + off < 32) suf += v;
    }
    if (lane == 0) warpsum[warp] = suf;
    __syncthreads();
    if (warp == 0) {
        unsigned ws = warpsum[lane];
        unsigned s2 = ws;
        #pragma unroll
        for (int off = 1; off < 32; off <<= 1) {
            unsigned v = __shfl_down_sync(FULL, s2, off);
            if (lane + off < 32) s2 += v;
        }
        warpsuf[lane] = s2 - ws;
    }
    __syncthreads();

    unsigned suffInc = suf + warpsuf[warp];
    unsigned above   = suffInc - c;
    if (above < PRE && suffInc >= PRE) {
        unsigned run = above;
        int base = t * 64;          // coarse bucket t = fine bins [t*64, t*64+64)
        for (int b = 63; b >= 0; b--) {
            run += g_hist[base + b];
            if (run >= PRE) { g_B = (unsigned)(base + b); break; }
        }
    }
}

// ---------------------------------------------------------------- compact candidates (bin >= threshold bin)
__global__ void k_compact() {
    int t = blockIdx.x * blockDim.x + threadIdx.x;
    if (t >= NA) return;
    unsigned key = g_keys[t];
    if ((key >> 16) >= g_B) {
        int p = atomicAdd(&g_cnt, 1);
        if (p < CAP) {
            int a = t / NLOC, loc = t % NLOC;
            unsigned ai = (unsigned)(loc * 9 + a);
            g_cand[p] = ((u64)key << 32) | (~ai);
        }
    }
}

// ---------------------------------------------------------------- 2D-parallel exact rank (partial counts via atomics)
__global__ void k_rank2d() {
    __shared__ u64 tile[256];
    int cnt = g_cnt; if (cnt > CAP) cnt = CAP;
    if (blockIdx.x * 256 >= cnt || blockIdx.y * 256 >= cnt) return;  // uniform early exit
    int j = blockIdx.y * 256 + threadIdx.x;
    tile[threadIdx.x] = (j < cnt) ? g_cand[j] : 0ULL;   // zeros never beat valid keys
    __syncthreads();
    int p = blockIdx.x * 256 + threadIdx.x;
    if (p >= cnt) return;
    u64 v = g_cand[p];
    int r = 0;
    #pragma unroll 8
    for (int q = 0; q < 256; q++) r += (tile[q] > v);
    if (r) atomicAdd(&g_rank[p], r);
}

// ---------------------------------------------------------------- scatter boxes to rank order
__global__ void k_scatter() {
    int cnt = g_cnt; if (cnt > CAP) cnt = CAP;
    int p = blockIdx.x * 256 + threadIdx.x;
    if (p >= cnt) return;
    int r = g_rank[p];
    if (r < PRE) {
        u64 v = g_cand[p];
        unsigned idx = ~(unsigned)v;
        g_top[r] = g_boxes[idx];
    }
}

// ---------------------------------------------------------------- IoU bitmask (upper-triangular) + state re-zero
__global__ void k_mask() {
    __shared__ float4 sb[64];
    int cb = blockIdx.x, rb = blockIdx.y, t = threadIdx.x;

    // housekeeping for the NEXT run: zero hist/coarse/rank/cnt (safe: all
    // consumers of these ran in earlier kernels of THIS run)
    {
        int bid = blockIdx.y * gridDim.x + blockIdx.x;
        int gt  = bid * 64 + t;
        if (gt < NBIN)                       g_hist[gt] = 0u;
        else if (gt < NBIN + NCO)            g_coarse[gt - NBIN] = 0u;
        else if (gt < NBIN + NCO + CAP)      g_rank[gt - NBIN - NCO] = 0;
        else if (gt == NBIN + NCO + CAP)     g_cnt = 0;
    }

    if (cb < rb) return;           // sub-diagonal: never written, never read
    int i = rb * 64 + t;
    int j0 = cb * 64;
    int jg = j0 + t;
    sb[t] = (jg < PRE) ? g_top[jg] : make_float4(0.f, 0.f, 0.f, 0.f);
    __syncthreads();
    if (i >= PRE) return;
    float4 bi = g_top[i];
    float ai = (bi.z - bi.x) * (bi.w - bi.y);
    u64 bits = 0ULL;
    #pragma unroll 4
    for (int b = 0; b < 64; b++) {
        int j = j0 + b;
        float4 bj = sb[b];
        float aj = (bj.z - bj.x) * (bj.w - bj.y);
        float lx = fmaxf(bi.x, bj.x), ly = fmaxf(bi.y, bj.y);
        float rx = fminf(bi.z, bj.z), ry = fminf(bi.w, bj.w);
        float ww = fmaxf(rx - lx, 0.f), hh = fmaxf(ry - ly, 0.f);
        float inter = ww * hh;
        float iou = inter / (ai + aj - inter);
        if (j > i && j < PRE && iou > 0.7f) bits |= 1ULL << b;
    }
    g_mask[(size_t)i * NW + cb] = bits;
}

// ================================================================ word-level NMS, chunk-phased pending buffer
// Per chunk: (1) commit pending row loads from previous chunk (one exposed
// latency per chunk, 8 independent loads in flight), (2) fold+broadcast word
// c, (3) extract keeps via smem diag only — every popped bit IS a keep, and
// suppressed candidates cost zero, (4) issue this chunk's row loads into an
// UNROLLED register buffer (constant indices — no local-memory spill).
__global__ __launch_bounds__(128) void k_nms(float* __restrict__ out) {
    extern __shared__ u64 diag[];      // [NW*64] : diag[j] = g_mask[j][j>>6]
    __shared__ int s_keep[POST];
    __shared__ int s_nk;

    int tid  = threadIdx.x;
    int lane = tid & 31;

    // parallel preload of diagonal blocks (4 warps)
    for (int i = tid; i < NW * 64; i += 128) {
        int c = i >> 6;
        diag[i] = (i < PRE) ? g_mask[(size_t)i * NW + c] : 0ULL;
    }
    __syncthreads();

    if (tid < 32) {
        // acc words (lane owns: lane, lane+32, lane+64)
        u64 acc0 = 0ULL, acc1 = 0ULL, acc2 = 0ULL;
        if (lane == 29) acc2 = (~0ULL) << 48;   // word 93: indices 6000..6015 invalid
        if (lane >= 30) acc2 = ~0ULL;           // words 94,95 don't exist

        u64 pv0[PB], pv1[PB], pv2[PB];
        #pragma unroll
        for (int m = 0; m < PB; m++) { pv0[m] = 0ULL; pv1[m] = 0ULL; pv2[m] = 0ULL; }

        int nk = 0;
        for (int c = 0; c < NW && nk < POST; c++) {
            // ---- commit pending loads from previous chunk (unrolled, regs)
            #pragma unroll
            for (int m = 0; m < PB; m++) { acc0 |= pv0[m]; acc1 |= pv1[m]; acc2 |= pv2[m]; }

            // ---- fold word c + broadcast
            u64 w = (c < 32) ? acc0 : ((c < 64) ? acc1 : acc2);
            u64 freew = ~__shfl_sync(FULL, w, c & 31);

            // ---- extract keeps (smem diag only; each pop = one keep)
            u64 keptw = 0ULL;
            while (freew && nk < POST) {
                int b = __ffsll((long long)freew) - 1;
                int j = (c << 6) + b;
                if (lane == 0) s_keep[nk] = j;
                nk++;
                u64 bit = 1ULL << b;
                keptw |= bit;
                freew &= ~(diag[j] | bit);
            }

            // ---- issue row loads for up to PB keeps (unrolled -> registers)
            u64 kb = keptw;
            #pragma unroll
            for (int m = 0; m < PB; m++) {
                if (kb) {
                    int b = __ffsll((long long)kb) - 1; kb &= kb - 1;
                    const u64* row = g_mask + (size_t)((c << 6) + b) * NW;
                    pv0[m] = (lane      >= c + 1)                   ? row[lane]      : 0ULL;
                    pv1[m] = (lane + 32 >= c + 1)                   ? row[lane + 32] : 0ULL;
                    pv2[m] = (lane + 64 >= c + 1 && lane + 64 < NW) ? row[lane + 64] : 0ULL;
                } else { pv0[m] = 0ULL; pv1[m] = 0ULL; pv2[m] = 0ULL; }
            }
            // overflow (>PB keeps in one chunk): immediate OR (rare)
            while (kb) {
                int b = __ffsll((long long)kb) - 1; kb &= kb - 1;
                const u64* row = g_mask + (size_t)((c << 6) + b) * NW;
                if (lane      >= c + 1)                   acc0 |= row[lane];
                if (lane + 32 >= c + 1)                   acc1 |= row[lane + 32];
                if (lane + 64 >= c + 1 && lane + 64 < NW) acc2 |= row[lane + 64];
            }
        }
        if (lane == 0) s_nk = nk;
    }
    __syncthreads();
    int nk = s_nk;
    for (int k = tid; k < POST; k += 128) if (k >= nk) s_keep[k] = 0;
    __syncthreads();
    for (int k = tid; k < POST; k += 128) {
        float4 b = g_top[s_keep[k]];
        out[k * 5 + 0] = 0.f;
        out[k * 5 + 1] = b.x;
        out[k * 5 + 2] = b.y;
        out[k * 5 + 3] = b.z;
        out[k * 5 + 4] = b.w;
    }
}

// ---------------------------------------------------------------- launch
extern "C" void kernel_launch(void* const* d_in, const int* in_sizes, int n_in,
                              void* d_out, int out_size) {
    const float* cls  = (const float*)d_in[0];
    const float* bbox = (const float*)d_in[1];
    const int*   ih   = (const int*)d_in[2];
    const int*   iw   = (const int*)d_in[3];
    float* out = (float*)d_out;

    static bool attr_set = false;
    if (!attr_set) {
        cudaFuncSetAttribute(k_nms, cudaFuncAttributeMaxDynamicSharedMemorySize,
                             NW * 64 * (int)sizeof(u64) + 4096);
        attr_set = true;
    }

    k_decode <<<(NA + 255) / 256, 256>>>(cls, bbox, ih, iw);
    k_thresh <<<1, 1024>>>();
    k_compact<<<(NA + 255) / 256, 256>>>();
    k_rank2d <<<dim3(CAP / 256, CAP / 256), 256>>>();
    k_scatter<<<CAP / 256, 256>>>();
    k_mask   <<<dim3(NW, NW), 64>>>();
    k_nms    <<<1, 128, NW * 64 * sizeof(u64)>>>(out);
}

// round 17
// speedup vs baseline: 2.9576x; 1.7817x over previous
#include <cuda_runtime.h>
#include <cstdint>

#define NA    57600     // 64*100*9 anchors
#define NLOC  6400      // 64*100
#define FW    100
#define PRE   6000
#define POST  300
#define NW    94        // ceil(6000/64) u64 words
#define CAP   8192
#define NBIN  65536
#define NCO   1024
#define FULL  0xFFFFFFFFu

typedef unsigned long long u64;

// Base anchors (ratios 0.5,1,2 x scales 8,16,32), numpy banker's rounding baked in.
__constant__ float c_base[36] = {
  -84.f,  -40.f,  99.f,  55.f,
 -176.f,  -88.f, 191.f, 103.f,
 -360.f, -184.f, 375.f, 199.f,
  -56.f,  -56.f,  71.f,  71.f,
 -120.f, -120.f, 135.f, 135.f,
 -248.f, -248.f, 263.f, 263.f,
  -36.f,  -80.f,  51.f,  95.f,
  -80.f, -168.f,  95.f, 183.f,
 -168.f, -344.f, 183.f, 359.f
};

// NOTE: g_hist/g_coarse/g_rank/g_cnt must be ZERO on entry to each run.
// They start zero (static init) and are re-zeroed by k_mask each run.
__device__ float4   g_boxes[NA];
__device__ unsigned g_keys[NA];
__device__ unsigned g_hist[NBIN];
__device__ unsigned g_coarse[NCO];
__device__ int      g_cnt;
__device__ unsigned g_B;
__device__ u64      g_cand[CAP];
__device__ int      g_rank[CAP];
__device__ float4   g_top[PRE];
__device__ u64      g_mask[(size_t)PRE * NW];   // triangular: words < i/64 of row i NOT written

// ---------------------------------------------------------------- decode + fine/coarse histograms
__global__ void k_decode(const float* __restrict__ cls,
                         const float* __restrict__ bbox,
                         const int*   __restrict__ ih,
                         const int*   __restrict__ iw) {
    int t = blockIdx.x * blockDim.x + threadIdx.x;
    if (t >= NA) return;
    int a = t / NLOC, loc = t % NLOC;       // coalesced channel reads
    int y = loc / FW, x = loc % FW;
    int ai = loc * 9 + a;                   // reference anchor index

    float s0 = cls[(2 * a)     * NLOC + loc];
    float s1 = cls[(2 * a + 1) * NLOC + loc];
    float m  = fmaxf(s0, s1);
    float e0 = expf(s0 - m), e1 = expf(s1 - m);
    float score = e1 / (e0 + e1);

    float dx = bbox[(4 * a + 0) * NLOC + loc];
    float dy = bbox[(4 * a + 1) * NLOC + loc];
    float dw = bbox[(4 * a + 2) * NLOC + loc];
    float dh = bbox[(4 * a + 3) * NLOC + loc];

    float sx = (float)(x * 16), sy = (float)(y * 16);
    float ax1 = sx + c_base[a * 4 + 0];
    float ay1 = sy + c_base[a * 4 + 1];
    float ax2 = sx + c_base[a * 4 + 2];
    float ay2 = sy + c_base[a * 4 + 3];

    float w  = ax2 - ax1 + 1.0f;
    float h  = ay2 - ay1 + 1.0f;
    float cx = ax1 + 0.5f * w;
    float cy = ay1 + 0.5f * h;

    float pcx = dx * w + cx;
    float pcy = dy * h + cy;
    float pw  = expf(dw) * w;
    float ph  = expf(dh) * h;

    float W = (float)(iw[0] - 1);
    float H = (float)(ih[0] - 1);
    float x1 = fminf(fmaxf(pcx - 0.5f * pw, 0.f), W);
    float y1 = fminf(fmaxf(pcy - 0.5f * ph, 0.f), H);
    float x2 = fminf(fmaxf(pcx + 0.5f * pw, 0.f), W);
    float y2 = fminf(fmaxf(pcy + 0.5f * ph, 0.f), H);

    bool valid = (x2 - x1 + 1.f >= 16.f) && (y2 - y1 + 1.f >= 16.f);
    float s = valid ? score : -1e30f;

    unsigned u = __float_as_uint(s);
    unsigned key = (u & 0x80000000u) ? ~u : (u | 0x80000000u);

    g_keys[t]   = key;
    g_boxes[ai] = make_float4(x1, y1, x2, y2);
    atomicAdd(&g_hist[key >> 16], 1u);
    atomicAdd(&g_coarse[key >> 22], 1u);
}

// ---------------------------------------------------------------- threshold bin via coarse hist (1 block)
__global__ void k_thresh() {
    __shared__ unsigned warpsum[32];
    __shared__ unsigned warpsuf[32];
    int t = threadIdx.x;            // 1024 threads, one per coarse bucket
    int lane = t & 31, warp = t >> 5;

    unsigned c = g_coarse[t];

    unsigned suf = c;
    #pragma unroll
    for (int off = 1; off < 32; off <<= 1) {
        unsigned v = __shfl_down_sync(FULL, suf, off);
        if (lane + off < 32) suf += v;
    }
    if (lane == 0) warpsum[warp] = suf;
    __syncthreads();
    if (warp == 0) {
        unsigned ws = warpsum[lane];
        unsigned s2 = ws;
        #pragma unroll
        for (int off = 1; off < 32; off <<= 1) {
            unsigned v = __shfl_down_sync(FULL, s2, off);
            if (lane + off < 32) s2 += v;
        }
        warpsuf[lane] = s2 - ws;
    }
    __syncthreads();

    unsigned suffInc = suf + warpsuf[warp];
    unsigned above   = suffInc - c;
    if (above < PRE && suffInc >= PRE) {
        unsigned run = above;
        int base = t * 64;          // coarse bucket t = fine bins [t*64, t*64+64)
        for (int b = 63; b >= 0; b--) {
            run += g_hist[base + b];
            if (run >= PRE) { g_B = (unsigned)(base + b); break; }
        }
    }
}

// ---------------------------------------------------------------- compact candidates (bin >= threshold bin)
__global__ void k_compact() {
    int t = blockIdx.x * blockDim.x + threadIdx.x;
    if (t >= NA) return;
    unsigned key = g_keys[t];
    if ((key >> 16) >= g_B) {
        int p = atomicAdd(&g_cnt, 1);
        if (p < CAP) {
            int a = t / NLOC, loc = t % NLOC;
            unsigned ai = (unsigned)(loc * 9 + a);
            g_cand[p] = ((u64)key << 32) | (~ai);
        }
    }
}

// ---------------------------------------------------------------- 2D-parallel exact rank (partial counts via atomics)
__global__ void k_rank2d() {
    __shared__ u64 tile[256];
    int cnt = g_cnt; if (cnt > CAP) cnt = CAP;
    if (blockIdx.x * 256 >= cnt || blockIdx.y * 256 >= cnt) return;  // uniform early exit
    int j = blockIdx.y * 256 + threadIdx.x;
    tile[threadIdx.x] = (j < cnt) ? g_cand[j] : 0ULL;   // zeros never beat valid keys
    __syncthreads();
    int p = blockIdx.x * 256 + threadIdx.x;
    if (p >= cnt) return;
    u64 v = g_cand[p];
    int r = 0;
    #pragma unroll 8
    for (int q = 0; q < 256; q++) r += (tile[q] > v);
    if (r) atomicAdd(&g_rank[p], r);
}

// ---------------------------------------------------------------- scatter boxes to rank order
__global__ void k_scatter() {
    int cnt = g_cnt; if (cnt > CAP) cnt = CAP;
    int p = blockIdx.x * 256 + threadIdx.x;
    if (p >= cnt) return;
    int r = g_rank[p];
    if (r < PRE) {
        u64 v = g_cand[p];
        unsigned idx = ~(unsigned)v;
        g_top[r] = g_boxes[idx];
    }
}

// ---------------------------------------------------------------- IoU bitmask (upper-triangular) + state re-zero
__global__ void k_mask() {
    __shared__ float4 sb[64];
    int cb = blockIdx.x, rb = blockIdx.y, t = threadIdx.x;

    // housekeeping for the NEXT run: zero hist/coarse/rank/cnt (safe: all
    // consumers of these ran in earlier kernels of THIS run)
    {
        int bid = blockIdx.y * gridDim.x + blockIdx.x;
        int gt  = bid * 64 + t;
        if (gt < NBIN)                       g_hist[gt] = 0u;
        else if (gt < NBIN + NCO)            g_coarse[gt - NBIN] = 0u;
        else if (gt < NBIN + NCO + CAP)      g_rank[gt - NBIN - NCO] = 0;
        else if (gt == NBIN + NCO + CAP)     g_cnt = 0;
    }

    if (cb < rb) return;           // sub-diagonal: never written, never read
    int i = rb * 64 + t;
    int j0 = cb * 64;
    int jg = j0 + t;
    sb[t] = (jg < PRE) ? g_top[jg] : make_float4(0.f, 0.f, 0.f, 0.f);
    __syncthreads();
    if (i >= PRE) return;
    float4 bi = g_top[i];
    float ai = (bi.z - bi.x) * (bi.w - bi.y);
    u64 bits = 0ULL;
    #pragma unroll 4
    for (int b = 0; b < 64; b++) {
        int j = j0 + b;
        float4 bj = sb[b];
        float aj = (bj.z - bj.x) * (bj.w - bj.y);
        float lx = fmaxf(bi.x, bj.x), ly = fmaxf(bi.y, bj.y);
        float rx = fminf(bi.z, bj.z), ry = fminf(bi.w, bj.w);
        float ww = fmaxf(rx - lx, 0.f), hh = fmaxf(ry - ly, 0.f);
        float inter = ww * hh;
        float iou = inter / (ai + aj - inter);
        if (j > i && j < PRE && iou > 0.7f) bits |= 1ULL << b;
    }
    g_mask[(size_t)i * NW + cb] = bits;
}

// ================================================================ block-parallel on-demand NMS
// Per chunk c: remw = OR over all kept j (j < c*64) of mask[j][c], computed by
// 256 threads in PARALLEL (<=2 loads each, one exposed latency per chunk,
// independent of keep count). Chunk's diagonal block loaded concurrently.
// Thread 0 then extracts this chunk's keeps via the smem diag chain —
// suppressed candidates cost zero. Exact greedy semantics.
__global__ __launch_bounds__(256) void k_nms(float* __restrict__ out) {
    __shared__ int s_keep[POST];
    __shared__ int s_nk;
    __shared__ u64 s_diag[64];
    __shared__ u64 s_part[8];

    int tid = threadIdx.x, lane = tid & 31, warp = tid >> 5;
    if (tid == 0) s_nk = 0;
    __syncthreads();

    for (int c = 0; c < NW; c++) {
        int nk = s_nk;
        // ---- parallel fold of word c over all keeps so far (independent loads)
        u64 v = 0ULL;
        for (int k = tid; k < nk; k += 256)
            v |= g_mask[(size_t)s_keep[k] * NW + c];
        // ---- concurrent diag load for this chunk (threads 192..255)
        if (tid >= 192) {
            int b = tid - 192;
            int j = (c << 6) + b;
            s_diag[b] = (j < PRE) ? g_mask[(size_t)j * NW + c] : ~0ULL;
        }
        // ---- OR-reduce
        #pragma unroll
        for (int off = 16; off; off >>= 1)
            v |= __shfl_xor_sync(FULL, v, off);
        if (lane == 0) s_part[warp] = v;
        __syncthreads();
        // ---- serial extract (thread 0): every popped bit is a keep
        if (tid == 0) {
            u64 w = s_part[0] | s_part[1] | s_part[2] | s_part[3] |
                    s_part[4] | s_part[5] | s_part[6] | s_part[7];
            u64 freew = ~w;
            if (c == NW - 1) freew &= (1ULL << 48) - 1;   // indices 6000..6015 invalid
            int cnt = nk;
            while (freew && cnt < POST) {
                int b = __ffsll((long long)freew) - 1;
                s_keep[cnt++] = (c << 6) + b;
                freew &= ~(s_diag[b] | (1ULL << b));
            }
            s_nk = cnt;
        }
        __syncthreads();
        if (s_nk >= POST) break;
    }

    int nk = s_nk;
    for (int k = tid; k < POST; k += 256) if (k >= nk) s_keep[k] = 0;
    __syncthreads();
    for (int k = tid; k < POST; k += 256) {
        float4 b = g_top[s_keep[k]];
        out[k * 5 + 0] = 0.f;
        out[k * 5 + 1] = b.x;
        out[k * 5 + 2] = b.y;
        out[k * 5 + 3] = b.z;
        out[k * 5 + 4] = b.w;
    }
}

// ---------------------------------------------------------------- launch
extern "C" void kernel_launch(void* const* d_in, const int* in_sizes, int n_in,
                              void* d_out, int out_size) {
    const float* cls  = (const float*)d_in[0];
    const float* bbox = (const float*)d_in[1];
    const int*   ih   = (const int*)d_in[2];
    const int*   iw   = (const int*)d_in[3];
    float* out = (float*)d_out;

    k_decode <<<(NA + 255) / 256, 256>>>(cls, bbox, ih, iw);
    k_thresh <<<1, 1024>>>();
    k_compact<<<(NA + 255) / 256, 256>>>();
    k_rank2d <<<dim3(CAP / 256, CAP / 256), 256>>>();
    k_scatter<<<CAP / 256, 256>>>();
    k_mask   <<<dim3(NW, NW), 64>>>();
    k_nms    <<<1, 256>>>(out);
}